// round 2
// baseline (speedup 1.0000x reference)
#include <cuda_runtime.h>
#include <math.h>

// ---------------------------------------------------------------------------
// InteractionPredictor e3nn-GNN forward, fp32.
// S=16 scalars, V=8 vectors (GEO=24), node feature = 40 floats.
// ---------------------------------------------------------------------------
#define NMAX 16384
__device__ float g_nodeA[NMAX * 40];
__device__ float g_nodeB[NMAX * 40];
__device__ float g_msgs [NMAX * 40];
__device__ __align__(16) float g_tw[320 * 512];   // transposed rec_w1

#define ACT_NORM 1.6789717f
#define PW0_8    0.025515518153991443f   // sqrt(1/24)/8  (== pw1/sqrt3/8)
#define PW1_8    0.044194173824159216f   // sqrt(1/8)/8
#define PWREC_8  0.006987712429686843f   // sqrt(1/320)/8
#define INV_SQ3  0.57735026918962576f
#define DEMB_C   37.716086f              // 1.14136 * e^2 * sqrt(20)

__device__ __forceinline__ float silu_act(float s) {
    return s / (1.f + expf(-s)) * ACT_NORM;
}

// ---------------------------------------------------------------------------
// Transpose rec_w1 [64,2560] -> TW[320,512], TW[p][k*8+w] = rw1[k][p*8+w]
// ---------------------------------------------------------------------------
__global__ void k_transpose(const float* __restrict__ rw1) {
    int idx = blockIdx.x * 256 + threadIdx.x;
    if (idx >= 320 * 512) return;
    int p = idx >> 9, r = idx & 511;
    int k = r >> 3, w = r & 7;
    g_tw[idx] = rw1[k * 2560 + p * 8 + w];
}

// ---------------------------------------------------------------------------
// Node embedding MLP + zero geo + zero msgs. One warp per node.
// ---------------------------------------------------------------------------
__global__ void k_embed(const float* __restrict__ x,
                        const float* __restrict__ w0,   // [10,64]
                        const float* __restrict__ w1,   // [64,16]
                        int N) {
    __shared__ float sh[8][64];
    int warp = threadIdx.x >> 5, lane = threadIdx.x & 31;
    int n = blockIdx.x * 8 + warp;
    if (n >= N) return;
    float xa[10];
    #pragma unroll
    for (int a = 0; a < 10; a++) xa[a] = x[n * 10 + a];
    #pragma unroll
    for (int r = 0; r < 2; r++) {
        int k = lane + r * 32;
        float s = 0.f;
        #pragma unroll
        for (int a = 0; a < 10; a++) s += xa[a] * w0[a * 64 + k];
        sh[warp][k] = silu_act(s * 0.31622776601683794f);   // 1/sqrt(10)
    }
    __syncwarp();
    if (lane < 16) {
        float s = 0.f;
        #pragma unroll
        for (int k = 0; k < 64; k++) s += sh[warp][k] * w1[k * 16 + lane];
        g_nodeA[n * 40 + lane] = s * 0.125f;                // 1/sqrt(64)
    }
    if (lane < 24) g_nodeA[n * 40 + 16 + lane] = 0.f;
    g_msgs[n * 40 + lane] = 0.f;
    if (lane < 8) g_msgs[n * 40 + 32 + lane] = 0.f;
}

// ---------------------------------------------------------------------------
// Message pass: 32-edge tile per block, 256 threads.
//   h = hidden(edge_attr)  -> w = h @ mw1 (smem only) -> TP -> atomicAdd dst
// ---------------------------------------------------------------------------
__global__ void __launch_bounds__(256) k_msg(
        const float* __restrict__ pos,
        const int* __restrict__ src, const int* __restrict__ dst,
        const float* __restrict__ eattr,
        const float* __restrict__ mw0,   // [5,64]
        const float* __restrict__ mw1,   // [64,576]
        int E, int use_b) {
    extern __shared__ float sm[];
    float* sh_h   = sm;                 // 32*64  = 2048
    float* sh_f   = sh_h   + 2048;      // 32*40  = 1280
    float* sh_dot = sh_f   + 1280;      // 32*8   = 256
    float* sh_r   = sh_dot + 256;       // 32*3   = 96
    float* sh_w   = sh_r   + 96;        // 32*577 = 18464
    int*   sh_src = (int*)(sh_w + 18464);
    int*   sh_dst = sh_src + 32;

    const float* node = use_b ? g_nodeB : g_nodeA;
    int t = threadIdx.x;
    int ebase = blockIdx.x * 32;

    if (t < 32) {
        int eid = ebase + t;
        int sv = 0, dv = -1;
        if (eid < E) { sv = src[eid]; dv = dst[eid]; }
        sh_src[t] = sv; sh_dst[t] = dv;
    }
    __syncthreads();

    for (int idx = t; idx < 1280; idx += 256) {
        int e = idx / 40, f = idx - e * 40;
        sh_f[idx] = (sh_dst[e] >= 0) ? node[sh_src[e] * 40 + f] : 0.f;
    }
    if (t < 32) {
        float rx = 0.f, ry = 0.f, rz = 0.f;
        if (sh_dst[t] >= 0) {
            const float* ps = pos + sh_src[t] * 3;
            const float* pd = pos + sh_dst[t] * 3;
            rx = pd[0] - ps[0]; ry = pd[1] - ps[1]; rz = pd[2] - ps[2];
            float inv = rsqrtf(rx * rx + ry * ry + rz * rz);
            rx *= inv; ry *= inv; rz *= inv;
        }
        sh_r[t * 3] = rx; sh_r[t * 3 + 1] = ry; sh_r[t * 3 + 2] = rz;
    }
    // hidden layer: thread (e = t>>3) owns k = (t&7)*8..+7
    {
        int e = t >> 3, kb = (t & 7) * 8;
        int eid = ebase + e;
        bool valid = eid < E;
        float ea[5];
        #pragma unroll
        for (int a = 0; a < 5; a++) ea[a] = valid ? eattr[eid * 5 + a] : 0.f;
        #pragma unroll
        for (int kk = 0; kk < 8; kk++) {
            int k = kb + kk;
            float s = 0.f;
            #pragma unroll
            for (int a = 0; a < 5; a++) s += ea[a] * mw0[a * 64 + k];
            sh_h[e * 64 + k] = valid ? silu_act(s * 0.4472135954999579f) : 0.f;
        }
    }
    __syncthreads();

    // xv . rhat
    if (t < 256) {
        int e = t >> 3, u = t & 7;
        sh_dot[t] = sh_f[e * 40 + 16 + u * 3]     * sh_r[e * 3]
                  + sh_f[e * 40 + 17 + u * 3]     * sh_r[e * 3 + 1]
                  + sh_f[e * 40 + 18 + u * 3]     * sh_r[e * 3 + 2];
    }
    __syncthreads();

    // GEMM sh_w[e][576] = sh_h[e][64] @ mw1
    {
        int jl = t & 15, eg = t >> 4;
        int e0 = eg * 2;
        for (int jb = 0; jb < 9; jb++) {
            int j = jb * 64 + jl * 4;
            float a0 = 0, a1 = 0, a2 = 0, a3 = 0, b0 = 0, b1 = 0, b2 = 0, b3 = 0;
            const float4* wp = (const float4*)(mw1 + j);
            #pragma unroll 4
            for (int k = 0; k < 64; k++) {
                float4 w = wp[k * 144];
                float h0 = sh_h[e0 * 64 + k];
                float h1 = sh_h[e0 * 64 + 64 + k];
                a0 += h0 * w.x; a1 += h0 * w.y; a2 += h0 * w.z; a3 += h0 * w.w;
                b0 += h1 * w.x; b1 += h1 * w.y; b2 += h1 * w.z; b3 += h1 * w.w;
            }
            float* o0 = sh_w + e0 * 577 + j;
            float* o1 = o0 + 577;
            o0[0] = a0; o0[1] = a1; o0[2] = a2; o0[3] = a3;
            o1[0] = b0; o1[1] = b1; o1[2] = b2; o1[3] = b3;
        }
    }
    __syncthreads();

    // TP contraction + scatter
    for (int idx = t; idx < 1280; idx += 256) {
        int e = idx / 40, o = idx - e * 40;
        int d = sh_dst[e];
        if (d < 0) continue;
        const float* w = sh_w + e * 577;
        const float* f = sh_f + e * 40;
        float val;
        if (o < 16) {
            float s1 = 0.f, s2 = 0.f;
            #pragma unroll
            for (int u = 0; u < 16; u++) s1 += f[u] * w[u * 16 + o];
            #pragma unroll
            for (int u = 0; u < 8; u++)  s2 += sh_dot[e * 8 + u] * w[256 + u * 16 + o];
            val = PW0_8 * (s1 + s2);
        } else {
            int v = o - 16; int wv = v / 3; int i = v - wv * 3;
            float s1 = 0.f, s2 = 0.f;
            #pragma unroll
            for (int u = 0; u < 16; u++) s1 += f[u] * w[384 + u * 8 + wv];
            #pragma unroll
            for (int u = 0; u < 8; u++)  s2 += f[16 + u * 3 + i] * w[512 + u * 8 + wv];
            val = PW1_8 * s1 * sh_r[e * 3 + i] + PW0_8 * s2;
        }
        atomicAdd(&g_msgs[d * 40 + o], val);
    }
}

// ---------------------------------------------------------------------------
// Update step: msgs*imp/sqrt(deg), update MLP on scalars, geo residual.
// step=0: A->B (gscale 1); step=1: B->A (gscale 0.5). Re-zeroes g_msgs.
// ---------------------------------------------------------------------------
__global__ void k_upd(const float* __restrict__ uw0,   // [32,64]
                      const float* __restrict__ uw1,   // [64,16]
                      const float* __restrict__ imp,
                      int N, float degInv, int step) {
    __shared__ float cat[8][32];
    __shared__ float hh[8][64];
    int warp = threadIdx.x >> 5, lane = threadIdx.x & 31;
    int n = blockIdx.x * 8 + warp;
    if (n >= N) return;
    const float* in = step ? g_nodeB : g_nodeA;
    float* out = step ? g_nodeA : g_nodeB;
    float sc = imp[0] * degInv;
    float gscale = step ? 0.5f : 1.0f;
    if (lane < 16) {
        cat[warp][lane]      = g_msgs[n * 40 + lane] * sc;
        cat[warp][16 + lane] = in[n * 40 + lane];
    }
    __syncwarp();
    #pragma unroll
    for (int r = 0; r < 2; r++) {
        int k = lane + r * 32;
        float s = 0.f;
        #pragma unroll
        for (int a = 0; a < 32; a++) s += cat[warp][a] * uw0[a * 64 + k];
        hh[warp][k] = silu_act(s * 0.17677669529663687f);   // 1/sqrt(32)
    }
    __syncwarp();
    if (lane < 16) {
        float s = 0.f;
        #pragma unroll
        for (int k = 0; k < 64; k++) s += hh[warp][k] * uw1[k * 16 + lane];
        out[n * 40 + lane] = s * 0.125f;
    }
    if (lane < 24)
        out[n * 40 + 16 + lane] =
            (g_msgs[n * 40 + 16 + lane] * sc + in[n * 40 + 16 + lane]) * gscale;
    g_msgs[n * 40 + lane] = 0.f;
    if (lane < 8) g_msgs[n * 40 + 32 + lane] = 0.f;
}

// ---------------------------------------------------------------------------
// Final: 16 inter-edges per block. demb -> two hidden layers -> lig TP ->
// Z[320] -> Z @ TW[320,512] -> dot with h_rec -> out[8].
// ---------------------------------------------------------------------------
__global__ void __launch_bounds__(256) k_final(
        const float* __restrict__ pos,
        const int* __restrict__ irec, const int* __restrict__ ilig,
        const float* __restrict__ lw0,   // [20,64]
        const float* __restrict__ lw1,   // [64,576]
        const float* __restrict__ rw0,   // [20,64]
        float* __restrict__ outp, int EI) {
    extern __shared__ float sm[];
    float* sh_demb = sm;                  // 320
    float* sh_hl   = sh_demb + 320;       // 1024
    float* sh_hr   = sh_hl + 1024;        // 1024
    float* sh_wl   = sh_hr + 1024;        // 9232
    float* sh_fl   = sh_wl + 9232;        // 640
    float* sh_fr   = sh_fl + 640;         // 640
    float* sh_r    = sh_fr + 640;         // 48
    float* sh_d    = sh_r + 48;           // 16
    float* sh_dot  = sh_d + 16;           // 128
    float* sh_le   = sh_dot + 128;        // 640
    float* sh_z    = sh_le + 640;         // 5120
    float* sh_po   = sh_z + 5120;         // 1024
    int* sh_ir = (int*)(sh_po + 1024);
    int* sh_il = sh_ir + 16;

    int t = threadIdx.x;
    int e = t >> 4, c = t & 15;
    int ebase = blockIdx.x * 16;

    if (t < 16) {
        int id = ebase + t;
        sh_ir[t] = (id < EI) ? irec[id] : 0;
        sh_il[t] = (id < EI) ? ilig[id] : 0;
    }
    __syncthreads();
    for (int idx = t; idx < 640; idx += 256) {
        int ee = idx / 40, f = idx - ee * 40;
        sh_fl[idx] = g_nodeA[sh_il[ee] * 40 + f];
        sh_fr[idx] = g_nodeA[sh_ir[ee] * 40 + f];
    }
    if (t < 16) {
        bool valid = (ebase + t) < EI;
        const float* pr = pos + sh_ir[t] * 3;
        const float* pl = pos + sh_il[t] * 3;
        float rx = pl[0] - pr[0], ry = pl[1] - pr[1], rz = pl[2] - pr[2];
        float d = sqrtf(rx * rx + ry * ry + rz * rz);
        float inv = (valid && d > 0.f) ? 1.f / d : 0.f;
        sh_r[t * 3] = rx * inv; sh_r[t * 3 + 1] = ry * inv; sh_r[t * 3 + 2] = rz * inv;
        sh_d[t] = valid ? d : 1e9f;
    }
    __syncthreads();
    for (int idx = t; idx < 320; idx += 256) {
        int ee = idx / 20, a = idx - ee * 20;
        float diff = sh_d[ee] * (21.f / 5.f) - (float)(a + 1);
        float t1 = diff + 1.f, t2 = 1.f - diff;
        float v = 0.f;
        if (t1 > 0.f && t2 > 0.f) v = DEMB_C * expf(-1.f / t1 - 1.f / t2);
        sh_demb[idx] = v;
    }
    __syncthreads();
    {   // two hidden layers (fan-in 20)
        float da[20];
        #pragma unroll
        for (int a = 0; a < 20; a++) da[a] = sh_demb[e * 20 + a];
        #pragma unroll
        for (int kk = 0; kk < 4; kk++) {
            int k = c * 4 + kk;
            float s1 = 0.f, s2 = 0.f;
            #pragma unroll
            for (int a = 0; a < 20; a++) {
                s1 += da[a] * lw0[a * 64 + k];
                s2 += da[a] * rw0[a * 64 + k];
            }
            sh_hl[e * 64 + k] = silu_act(s1 * 0.22360679774997896f);  // 1/sqrt(20)
            sh_hr[e * 64 + k] = silu_act(s2 * 0.22360679774997896f);
        }
    }
    if (t < 128) {
        int ee = t >> 3, u = t & 7;
        sh_dot[t] = sh_fl[ee * 40 + 16 + u * 3]     * sh_r[ee * 3]
                  + sh_fl[ee * 40 + 17 + u * 3]     * sh_r[ee * 3 + 1]
                  + sh_fl[ee * 40 + 18 + u * 3]     * sh_r[ee * 3 + 2];
    }
    __syncthreads();
    {   // wlig = h_lig @ lig_w1
        const float4* wp = (const float4*)lw1;
        #pragma unroll
        for (int jb = 0; jb < 9; jb++) {
            float a0 = 0, a1 = 0, a2 = 0, a3 = 0;
            #pragma unroll 4
            for (int k = 0; k < 64; k++) {
                float4 w4 = wp[k * 144 + jb * 16 + c];
                float h = sh_hl[e * 64 + k];
                a0 += h * w4.x; a1 += h * w4.y; a2 += h * w4.z; a3 += h * w4.w;
            }
            float* o = sh_wl + e * 577 + jb * 64 + c * 4;
            o[0] = a0; o[1] = a1; o[2] = a2; o[3] = a3;
        }
    }
    __syncthreads();
    for (int idx = t; idx < 640; idx += 256) {   // lig_emb TP
        int ee = idx / 40, o = idx - ee * 40;
        const float* w = sh_wl + ee * 577;
        const float* f = sh_fl + ee * 40;
        float val;
        if (o < 16) {
            float s1 = 0.f, s2 = 0.f;
            #pragma unroll
            for (int u = 0; u < 16; u++) s1 += f[u] * w[u * 16 + o];
            #pragma unroll
            for (int u = 0; u < 8; u++)  s2 += sh_dot[ee * 8 + u] * w[256 + u * 16 + o];
            val = PW0_8 * (s1 + s2);
        } else {
            int v = o - 16; int wv = v / 3; int i = v - wv * 3;
            float s1 = 0.f, s2 = 0.f;
            #pragma unroll
            for (int u = 0; u < 16; u++) s1 += f[u] * w[384 + u * 8 + wv];
            #pragma unroll
            for (int u = 0; u < 8; u++)  s2 += f[16 + u * 3 + i] * w[512 + u * 8 + wv];
            val = PW1_8 * s1 * sh_r[ee * 3 + i] + PW0_8 * s2;
        }
        sh_le[idx] = val;
    }
    __syncthreads();
    for (int idx = t; idx < 5120; idx += 256) {  // Z vector
        int ee = idx / 320, p = idx - ee * 320;
        float z;
        if (p < 256) {
            z = sh_le[ee * 40 + (p >> 4)] * sh_fr[ee * 40 + (p & 15)];
        } else {
            int q = p - 256; int u = q >> 3, v = q & 7;
            z = (sh_le[ee * 40 + 16 + u * 3] * sh_fr[ee * 40 + 16 + v * 3]
               + sh_le[ee * 40 + 17 + u * 3] * sh_fr[ee * 40 + 17 + v * 3]
               + sh_le[ee * 40 + 18 + u * 3] * sh_fr[ee * 40 + 18 + v * 3]) * INV_SQ3;
        }
        sh_z[idx] = z;
    }
    __syncthreads();
    {   // M = Z @ TW, thread owns columns jj*64 + c*4 + x
        float m[32];
        #pragma unroll
        for (int i = 0; i < 32; i++) m[i] = 0.f;
        const float4* twp = (const float4*)g_tw;
        const float* zp = sh_z + e * 320;
        #pragma unroll 2
        for (int p = 0; p < 320; p++) {
            float z = zp[p];
            const float4* row = twp + p * 128 + c;
            #pragma unroll
            for (int jj = 0; jj < 8; jj++) {
                float4 w4 = row[jj * 16];
                m[jj * 4 + 0] += z * w4.x; m[jj * 4 + 1] += z * w4.y;
                m[jj * 4 + 2] += z * w4.z; m[jj * 4 + 3] += z * w4.w;
            }
        }
        // col j = jj*64 + c*4 + x  ->  k = jj*8 + (c>>1), w = (c&1)*4 + x
        int kc = c >> 1;
        float p0 = 0, p1 = 0, p2 = 0, p3 = 0;
        #pragma unroll
        for (int jj = 0; jj < 8; jj++) {
            float h = sh_hr[e * 64 + jj * 8 + kc];
            p0 += h * m[jj * 4];     p1 += h * m[jj * 4 + 1];
            p2 += h * m[jj * 4 + 2]; p3 += h * m[jj * 4 + 3];
        }
        float* o = sh_po + (e * 16 + c) * 4;
        o[0] = p0; o[1] = p1; o[2] = p2; o[3] = p3;
    }
    __syncthreads();
    if (t < 128) {
        int ee = t >> 3, w = t & 7;
        int id = ebase + ee;
        if (id < EI) {
            float s = 0.f;
            #pragma unroll
            for (int i = 0; i < 8; i++) {
                int cc = i * 2 + (w >> 2);          // even c -> w<4, odd c -> w>=4
                s += sh_po[(ee * 16 + cc) * 4 + (w & 3)];
            }
            outp[id * 8 + w] = PWREC_8 * s;
        }
    }
}

// ---------------------------------------------------------------------------
extern "C" void kernel_launch(void* const* d_in, const int* in_sizes, int n_in,
                              void* d_out, int out_size) {
    const float* x     = (const float*)d_in[0];
    const float* pos   = (const float*)d_in[1];
    const int*   eidx  = (const int*)  d_in[2];
    const float* eattr = (const float*)d_in[3];
    const int*   iidx  = (const int*)  d_in[4];
    const float* emb_w0= (const float*)d_in[5];
    const float* emb_w1= (const float*)d_in[6];
    const float* imp0  = (const float*)d_in[7];
    const float* m0w0  = (const float*)d_in[8];
    const float* m0w1  = (const float*)d_in[9];
    const float* u0w0  = (const float*)d_in[10];
    const float* u0w1  = (const float*)d_in[11];
    const float* imp1  = (const float*)d_in[12];
    const float* m1w0  = (const float*)d_in[13];
    const float* m1w1  = (const float*)d_in[14];
    const float* u1w0  = (const float*)d_in[15];
    const float* u1w1  = (const float*)d_in[16];
    const float* lw0   = (const float*)d_in[17];
    const float* lw1   = (const float*)d_in[18];
    const float* rw0   = (const float*)d_in[19];
    const float* rw1   = (const float*)d_in[20];
    float* outp = (float*)d_out;

    int N  = in_sizes[0] / 10;
    int E  = in_sizes[2] / 2;
    int EI = in_sizes[4] / 2;
    float degInv = (float)(1.0 / sqrt((double)E / (double)N));

    const int SM_MSG = (2048 + 1280 + 256 + 96 + 32 * 577) * 4 + 64 * 4;   // 88832
    const int SM_FIN = (320 + 1024 + 1024 + 9232 + 640 + 640 + 48 + 16 + 128
                        + 640 + 5120 + 1024) * 4 + 32 * 4;                 // 79552
    cudaFuncSetAttribute(k_msg,   cudaFuncAttributeMaxDynamicSharedMemorySize, SM_MSG);
    cudaFuncSetAttribute(k_final, cudaFuncAttributeMaxDynamicSharedMemorySize, SM_FIN);

    k_transpose<<<(320 * 512 + 255) / 256, 256>>>(rw1);
    k_embed<<<(N + 7) / 8, 256>>>(x, emb_w0, emb_w1, N);
    k_msg<<<(E + 31) / 32, 256, SM_MSG>>>(pos, eidx, eidx + E, eattr, m0w0, m0w1, E, 0);
    k_upd<<<(N + 7) / 8, 256>>>(u0w0, u0w1, imp0, N, degInv, 0);
    k_msg<<<(E + 31) / 32, 256, SM_MSG>>>(pos, eidx, eidx + E, eattr, m1w0, m1w1, E, 1);
    k_upd<<<(N + 7) / 8, 256>>>(u1w0, u1w1, imp1, N, degInv, 1);
    k_final<<<(EI + 15) / 16, 256, SM_FIN>>>(pos, iidx, iidx + EI, lw0, lw1, rw0, outp, EI);
}

// round 3
// speedup vs baseline: 2.9192x; 2.9192x over previous
#include <cuda_runtime.h>
#include <math.h>

// ---------------------------------------------------------------------------
// InteractionPredictor e3nn-GNN forward, fp32, GEMM-restructured.
// S=16 scalars, V=8 vectors (GEO=24), node feature = 40 floats.
// ---------------------------------------------------------------------------
#define NMAX  16384
#define EMAX  122880
#define EIMAX 40960

__device__ float g_nodeA[NMAX * 40];
__device__ float g_nodeB[NMAX * 40];
__device__ float g_msgs [NMAX * 40];
__device__ __align__(16) float g_tw[320 * 512];      // transposed rec_w1
__device__ __align__(16) float g_H [EMAX * 64];      // edge hidden
__device__ __align__(16) float g_Wg[(size_t)EMAX * 576];  // per-edge TP weights
__device__ __align__(16) float g_Hl[EIMAX * 64];
__device__ __align__(16) float g_Hr[EIMAX * 64];
__device__ __align__(16) float g_Z [(size_t)EIMAX * 320];
__device__ __align__(16) float g_M [(size_t)EIMAX * 512];
__device__ float g_rh[EIMAX * 3];

#define ACT_NORM 1.6789717f
#define PW0_8    0.025515518153991443f   // sqrt(1/24)/8  (== pw1/sqrt3/8)
#define PW1_8    0.044194173824159216f   // sqrt(1/8)/8
#define PWREC_8  0.006987712429686843f   // sqrt(1/320)/8
#define INV_SQ3  0.57735026918962576f
#define DEMB_C   37.716086f              // 1.14136 * e^2 * sqrt(20)

__device__ __forceinline__ float silu_act(float s) {
    return s / (1.f + expf(-s)) * ACT_NORM;
}

// ---------------------------------------------------------------------------
// Transpose rec_w1 [64,2560] -> TW[320,512], TW[p][k*8+w] = rw1[k][p*8+w]
// ---------------------------------------------------------------------------
__global__ void k_transpose(const float* __restrict__ rw1) {
    int idx = blockIdx.x * 256 + threadIdx.x;
    if (idx >= 320 * 512) return;
    int p = idx >> 9, r = idx & 511;
    int k = r >> 3, w = r & 7;
    g_tw[idx] = rw1[k * 2560 + p * 8 + w];
}

// ---------------------------------------------------------------------------
// Node embedding MLP + zero geo + zero msgs. One warp per node.
// ---------------------------------------------------------------------------
__global__ void k_embed(const float* __restrict__ x,
                        const float* __restrict__ w0,   // [10,64]
                        const float* __restrict__ w1,   // [64,16]
                        int N) {
    __shared__ float sh[8][64];
    int warp = threadIdx.x >> 5, lane = threadIdx.x & 31;
    int n = blockIdx.x * 8 + warp;
    if (n >= N) return;
    float xa[10];
    #pragma unroll
    for (int a = 0; a < 10; a++) xa[a] = x[n * 10 + a];
    #pragma unroll
    for (int r = 0; r < 2; r++) {
        int k = lane + r * 32;
        float s = 0.f;
        #pragma unroll
        for (int a = 0; a < 10; a++) s += xa[a] * w0[a * 64 + k];
        sh[warp][k] = silu_act(s * 0.31622776601683794f);   // 1/sqrt(10)
    }
    __syncwarp();
    if (lane < 16) {
        float s = 0.f;
        #pragma unroll
        for (int k = 0; k < 64; k++) s += sh[warp][k] * w1[k * 16 + lane];
        g_nodeA[n * 40 + lane] = s * 0.125f;                // 1/sqrt(64)
    }
    if (lane < 24) g_nodeA[n * 40 + 16 + lane] = 0.f;
    g_msgs[n * 40 + lane] = 0.f;
    if (lane < 8) g_msgs[n * 40 + 32 + lane] = 0.f;
}

// ---------------------------------------------------------------------------
// Edge hidden layer: H[e,k] = silu(eattr[e,:5] @ mw0 / sqrt5)
// ---------------------------------------------------------------------------
__global__ void k_hid_edge(const float* __restrict__ eattr,
                           const float* __restrict__ mw0,   // [5,64]
                           float* __restrict__ H, int E) {
    int idx = blockIdx.x * 256 + threadIdx.x;
    int e = idx >> 6, k = idx & 63;
    if (e >= E) return;
    float s = 0.f;
    #pragma unroll
    for (int a = 0; a < 5; a++) s += eattr[e * 5 + a] * mw0[a * 64 + k];
    H[idx] = silu_act(s * 0.4472135954999579f);             // 1/sqrt(5)
}

// ---------------------------------------------------------------------------
// Tiled SGEMM: C[M,N] = A[M,K] @ B[K,N], row-major, K%32==0, N%64==0.
// BM=128, BN=64, BK=32, 256 threads, 8x4 register tile.
// ---------------------------------------------------------------------------
__global__ void __launch_bounds__(256) k_gemm(const float* __restrict__ A,
                                              const float* __restrict__ B,
                                              float* __restrict__ C,
                                              int M, int N, int K) {
    __shared__ float As[32][132];   // transposed A tile, padded
    __shared__ float Bs[32][64];
    int t = threadIdx.x;
    int rowBase = blockIdx.y * 128;
    int nBase   = blockIdx.x * 64;
    int tx = t & 15, ty = t >> 4;
    int ar = t >> 3, ac4 = (t & 7) * 4;
    int bk = t >> 4, bn = (t & 15) * 4;
    float acc[8][4] = {};
    for (int k0 = 0; k0 < K; k0 += 32) {
        #pragma unroll
        for (int i = 0; i < 4; i++) {
            int r = rowBase + ar + 32 * i;
            float4 v = make_float4(0.f, 0.f, 0.f, 0.f);
            if (r < M) v = *(const float4*)(A + (size_t)r * K + k0 + ac4);
            As[ac4 + 0][ar + 32 * i] = v.x;
            As[ac4 + 1][ar + 32 * i] = v.y;
            As[ac4 + 2][ar + 32 * i] = v.z;
            As[ac4 + 3][ar + 32 * i] = v.w;
        }
        #pragma unroll
        for (int i = 0; i < 2; i++) {
            int kk = bk + 16 * i;
            *(float4*)&Bs[kk][bn] =
                *(const float4*)(B + (size_t)(k0 + kk) * N + nBase + bn);
        }
        __syncthreads();
        #pragma unroll
        for (int k = 0; k < 32; k++) {
            float4 b4 = *(float4*)&Bs[k][tx * 4];
            float4 a0 = *(float4*)&As[k][ty * 8];
            float4 a1 = *(float4*)&As[k][ty * 8 + 4];
            float av[8] = {a0.x, a0.y, a0.z, a0.w, a1.x, a1.y, a1.z, a1.w};
            #pragma unroll
            for (int i = 0; i < 8; i++) {
                acc[i][0] += av[i] * b4.x;
                acc[i][1] += av[i] * b4.y;
                acc[i][2] += av[i] * b4.z;
                acc[i][3] += av[i] * b4.w;
            }
        }
        __syncthreads();
    }
    #pragma unroll
    for (int i = 0; i < 8; i++) {
        int r = rowBase + ty * 8 + i;
        if (r < M)
            *(float4*)(C + (size_t)r * N + nBase + tx * 4) =
                make_float4(acc[i][0], acc[i][1], acc[i][2], acc[i][3]);
    }
}

// ---------------------------------------------------------------------------
// TP + scatter: 32 edges/block, w from global (coalesced), atomicAdd to msgs.
// ---------------------------------------------------------------------------
__global__ void __launch_bounds__(256) k_tp_scatter(
        const float* __restrict__ pos,
        const int* __restrict__ src, const int* __restrict__ dst,
        const float* __restrict__ Wg, int E, int use_b) {
    extern __shared__ float sm[];
    float* sh_w   = sm;                  // 32*577 = 18464
    float* sh_f   = sh_w + 18464;        // 1280
    float* sh_dot = sh_f + 1280;         // 256
    float* sh_r   = sh_dot + 256;        // 96
    int*   sh_src = (int*)(sh_r + 96);
    int*   sh_dst = sh_src + 32;
    const float* node = use_b ? g_nodeB : g_nodeA;
    int t = threadIdx.x;
    int ebase = blockIdx.x * 32;
    int nval = min(32, E - ebase);

    if (t < 32) {
        sh_src[t] = (t < nval) ? src[ebase + t] : 0;
        sh_dst[t] = (t < nval) ? dst[ebase + t] : -1;
    }
    __syncthreads();
    for (int idx = t; idx < nval * 576; idx += 256) {
        int e = idx / 576, j = idx - e * 576;
        sh_w[e * 577 + j] = Wg[(size_t)ebase * 576 + idx];
    }
    for (int idx = t; idx < 1280; idx += 256) {
        int e = idx / 40, f = idx - e * 40;
        sh_f[idx] = (sh_dst[e] >= 0) ? node[sh_src[e] * 40 + f] : 0.f;
    }
    if (t < 32) {
        float rx = 0.f, ry = 0.f, rz = 0.f;
        if (sh_dst[t] >= 0) {
            const float* ps = pos + sh_src[t] * 3;
            const float* pd = pos + sh_dst[t] * 3;
            rx = pd[0] - ps[0]; ry = pd[1] - ps[1]; rz = pd[2] - ps[2];
            float inv = rsqrtf(rx * rx + ry * ry + rz * rz);
            rx *= inv; ry *= inv; rz *= inv;
        }
        sh_r[t * 3] = rx; sh_r[t * 3 + 1] = ry; sh_r[t * 3 + 2] = rz;
    }
    __syncthreads();
    {
        int e = t >> 3, u = t & 7;
        sh_dot[t] = sh_f[e * 40 + 16 + u * 3] * sh_r[e * 3]
                  + sh_f[e * 40 + 17 + u * 3] * sh_r[e * 3 + 1]
                  + sh_f[e * 40 + 18 + u * 3] * sh_r[e * 3 + 2];
    }
    __syncthreads();
    for (int idx = t; idx < 1280; idx += 256) {
        int e = idx / 40, o = idx - e * 40;
        int d = sh_dst[e];
        if (d < 0) continue;
        const float* w = sh_w + e * 577;
        const float* f = sh_f + e * 40;
        float val;
        if (o < 16) {
            float s1 = 0.f, s2 = 0.f;
            #pragma unroll
            for (int u = 0; u < 16; u++) s1 += f[u] * w[u * 16 + o];
            #pragma unroll
            for (int u = 0; u < 8; u++)  s2 += sh_dot[e * 8 + u] * w[256 + u * 16 + o];
            val = PW0_8 * (s1 + s2);
        } else {
            int v = o - 16; int wv = v / 3; int i = v - wv * 3;
            float s1 = 0.f, s2 = 0.f;
            #pragma unroll
            for (int u = 0; u < 16; u++) s1 += f[u] * w[384 + u * 8 + wv];
            #pragma unroll
            for (int u = 0; u < 8; u++)  s2 += f[16 + u * 3 + i] * w[512 + u * 8 + wv];
            val = PW1_8 * s1 * sh_r[e * 3 + i] + PW0_8 * s2;
        }
        atomicAdd(&g_msgs[d * 40 + o], val);
    }
}

// ---------------------------------------------------------------------------
// Update step (same as validated R2). Re-zeroes g_msgs.
// ---------------------------------------------------------------------------
__global__ void k_upd(const float* __restrict__ uw0,   // [32,64]
                      const float* __restrict__ uw1,   // [64,16]
                      const float* __restrict__ imp,
                      int N, float degInv, int step) {
    __shared__ float cat[8][32];
    __shared__ float hh[8][64];
    int warp = threadIdx.x >> 5, lane = threadIdx.x & 31;
    int n = blockIdx.x * 8 + warp;
    if (n >= N) return;
    const float* in = step ? g_nodeB : g_nodeA;
    float* out = step ? g_nodeA : g_nodeB;
    float sc = imp[0] * degInv;
    float gscale = step ? 0.5f : 1.0f;
    if (lane < 16) {
        cat[warp][lane]      = g_msgs[n * 40 + lane] * sc;
        cat[warp][16 + lane] = in[n * 40 + lane];
    }
    __syncwarp();
    #pragma unroll
    for (int r = 0; r < 2; r++) {
        int k = lane + r * 32;
        float s = 0.f;
        #pragma unroll
        for (int a = 0; a < 32; a++) s += cat[warp][a] * uw0[a * 64 + k];
        hh[warp][k] = silu_act(s * 0.17677669529663687f);   // 1/sqrt(32)
    }
    __syncwarp();
    if (lane < 16) {
        float s = 0.f;
        #pragma unroll
        for (int k = 0; k < 64; k++) s += hh[warp][k] * uw1[k * 16 + lane];
        out[n * 40 + lane] = s * 0.125f;
    }
    if (lane < 24)
        out[n * 40 + 16 + lane] =
            (g_msgs[n * 40 + 16 + lane] * sc + in[n * 40 + 16 + lane]) * gscale;
    g_msgs[n * 40 + lane] = 0.f;
    if (lane < 8) g_msgs[n * 40 + 32 + lane] = 0.f;
}

// ---------------------------------------------------------------------------
// Inter-edge prep: rhat + dist-embed -> Hl, Hr hidden activations.
// 4 edges x 64 lanes per block.
// ---------------------------------------------------------------------------
__global__ void k_prep(const float* __restrict__ pos,
                       const int* __restrict__ irec, const int* __restrict__ ilig,
                       const float* __restrict__ lw0,   // [20,64]
                       const float* __restrict__ rw0,   // [20,64]
                       int EI) {
    int idx = blockIdx.x * 256 + threadIdx.x;
    int e = idx >> 6, k = idx & 63;
    if (e >= EI) return;
    int ir = irec[e], il = ilig[e];
    float rx = pos[il * 3]     - pos[ir * 3];
    float ry = pos[il * 3 + 1] - pos[ir * 3 + 1];
    float rz = pos[il * 3 + 2] - pos[ir * 3 + 2];
    float d = sqrtf(rx * rx + ry * ry + rz * rz);
    float inv = 1.f / d;
    if (k == 0) {
        g_rh[e * 3]     = rx * inv;
        g_rh[e * 3 + 1] = ry * inv;
        g_rh[e * 3 + 2] = rz * inv;
    }
    float s1 = 0.f, s2 = 0.f;
    #pragma unroll
    for (int a = 0; a < 20; a++) {
        float diff = d * (21.f / 5.f) - (float)(a + 1);
        float t1 = diff + 1.f, t2 = 1.f - diff;
        float v = 0.f;
        if (t1 > 0.f && t2 > 0.f) v = DEMB_C * expf(-1.f / t1 - 1.f / t2);
        s1 += v * lw0[a * 64 + k];
        s2 += v * rw0[a * 64 + k];
    }
    g_Hl[idx] = silu_act(s1 * 0.22360679774997896f);   // 1/sqrt(20)
    g_Hr[idx] = silu_act(s2 * 0.22360679774997896f);
}

// ---------------------------------------------------------------------------
// lig TP + Z outer-product: 16 inter-edges per block.
// ---------------------------------------------------------------------------
__global__ void __launch_bounds__(256) k_lig_tp_z(
        const int* __restrict__ irec, const int* __restrict__ ilig,
        const float* __restrict__ Wl, int EI) {
    extern __shared__ float sm[];
    float* sh_w   = sm;                 // 16*577 = 9232
    float* sh_fl  = sh_w + 9232;        // 640
    float* sh_fr  = sh_fl + 640;        // 640
    float* sh_dot = sh_fr + 640;        // 128
    float* sh_r   = sh_dot + 128;       // 48
    float* sh_le  = sh_r + 48;          // 640
    int* sh_il = (int*)(sh_le + 640);
    int* sh_ir = sh_il + 16;
    int t = threadIdx.x;
    int ebase = blockIdx.x * 16;
    int nval = min(16, EI - ebase);

    if (t < 16) {
        sh_ir[t] = (t < nval) ? irec[ebase + t] : 0;
        sh_il[t] = (t < nval) ? ilig[ebase + t] : 0;
    }
    __syncthreads();
    for (int idx = t; idx < nval * 576; idx += 256) {
        int e = idx / 576, j = idx - e * 576;
        sh_w[e * 577 + j] = Wl[(size_t)ebase * 576 + idx];
    }
    for (int idx = t; idx < 640; idx += 256) {
        int e = idx / 40, f = idx - e * 40;
        sh_fl[idx] = g_nodeA[sh_il[e] * 40 + f];
        sh_fr[idx] = g_nodeA[sh_ir[e] * 40 + f];
    }
    if (t < 48) {
        int e = t / 3;
        int ge = (e < nval) ? (ebase + e) : 0;
        sh_r[t] = g_rh[ge * 3 + (t - e * 3)];
    }
    __syncthreads();
    if (t < 128) {
        int e = t >> 3, u = t & 7;
        sh_dot[t] = sh_fl[e * 40 + 16 + u * 3] * sh_r[e * 3]
                  + sh_fl[e * 40 + 17 + u * 3] * sh_r[e * 3 + 1]
                  + sh_fl[e * 40 + 18 + u * 3] * sh_r[e * 3 + 2];
    }
    __syncthreads();
    for (int idx = t; idx < 640; idx += 256) {
        int e = idx / 40, o = idx - e * 40;
        const float* w = sh_w + e * 577;
        const float* f = sh_fl + e * 40;
        float val;
        if (o < 16) {
            float s1 = 0.f, s2 = 0.f;
            #pragma unroll
            for (int u = 0; u < 16; u++) s1 += f[u] * w[u * 16 + o];
            #pragma unroll
            for (int u = 0; u < 8; u++)  s2 += sh_dot[e * 8 + u] * w[256 + u * 16 + o];
            val = PW0_8 * (s1 + s2);
        } else {
            int v = o - 16; int wv = v / 3; int i = v - wv * 3;
            float s1 = 0.f, s2 = 0.f;
            #pragma unroll
            for (int u = 0; u < 16; u++) s1 += f[u] * w[384 + u * 8 + wv];
            #pragma unroll
            for (int u = 0; u < 8; u++)  s2 += f[16 + u * 3 + i] * w[512 + u * 8 + wv];
            val = PW1_8 * s1 * sh_r[e * 3 + i] + PW0_8 * s2;
        }
        sh_le[idx] = val;
    }
    __syncthreads();
    for (int idx = t; idx < nval * 320; idx += 256) {
        int e = idx / 320, p = idx - e * 320;
        float z;
        if (p < 256) {
            z = sh_le[e * 40 + (p >> 4)] * sh_fr[e * 40 + (p & 15)];
        } else {
            int q = p - 256; int u = q >> 3, v = q & 7;
            z = (sh_le[e * 40 + 16 + u * 3] * sh_fr[e * 40 + 16 + v * 3]
               + sh_le[e * 40 + 17 + u * 3] * sh_fr[e * 40 + 17 + v * 3]
               + sh_le[e * 40 + 18 + u * 3] * sh_fr[e * 40 + 18 + v * 3]) * INV_SQ3;
        }
        g_Z[(size_t)ebase * 320 + idx] = z;
    }
}

// ---------------------------------------------------------------------------
// Output: out[e,w] = PWREC_8 * sum_k Hr[e,k] * M[e,k*8+w]
// ---------------------------------------------------------------------------
__global__ void k_out(float* __restrict__ outp, int EI) {
    int idx = blockIdx.x * 256 + threadIdx.x;
    int e = idx >> 3, w = idx & 7;
    if (e >= EI) return;
    float s = 0.f;
    #pragma unroll
    for (int k = 0; k < 64; k++)
        s += g_Hr[e * 64 + k] * g_M[(size_t)e * 512 + k * 8 + w];
    outp[idx] = PWREC_8 * s;
}

// ---------------------------------------------------------------------------
extern "C" void kernel_launch(void* const* d_in, const int* in_sizes, int n_in,
                              void* d_out, int out_size) {
    const float* x     = (const float*)d_in[0];
    const float* pos   = (const float*)d_in[1];
    const int*   eidx  = (const int*)  d_in[2];
    const float* eattr = (const float*)d_in[3];
    const int*   iidx  = (const int*)  d_in[4];
    const float* emb_w0= (const float*)d_in[5];
    const float* emb_w1= (const float*)d_in[6];
    const float* imp0  = (const float*)d_in[7];
    const float* m0w0  = (const float*)d_in[8];
    const float* m0w1  = (const float*)d_in[9];
    const float* u0w0  = (const float*)d_in[10];
    const float* u0w1  = (const float*)d_in[11];
    const float* imp1  = (const float*)d_in[12];
    const float* m1w0  = (const float*)d_in[13];
    const float* m1w1  = (const float*)d_in[14];
    const float* u1w0  = (const float*)d_in[15];
    const float* u1w1  = (const float*)d_in[16];
    const float* lw0   = (const float*)d_in[17];
    const float* lw1   = (const float*)d_in[18];
    const float* rw0   = (const float*)d_in[19];
    const float* rw1   = (const float*)d_in[20];
    float* outp = (float*)d_out;

    int N  = in_sizes[0] / 10;
    int E  = in_sizes[2] / 2;
    int EI = in_sizes[4] / 2;
    float degInv = (float)(1.0 / sqrt((double)E / (double)N));

    float *pH, *pW, *pZ, *pM, *pHl, *pTW;
    cudaGetSymbolAddress((void**)&pH,  g_H);
    cudaGetSymbolAddress((void**)&pW,  g_Wg);
    cudaGetSymbolAddress((void**)&pZ,  g_Z);
    cudaGetSymbolAddress((void**)&pM,  g_M);
    cudaGetSymbolAddress((void**)&pHl, g_Hl);
    cudaGetSymbolAddress((void**)&pTW, g_tw);

    const int SM_TP  = (18464 + 1280 + 256 + 96) * 4 + 64 * 4;           // 80640
    const int SM_LIG = (9232 + 640 + 640 + 128 + 48 + 640) * 4 + 32 * 4; // 45440
    cudaFuncSetAttribute(k_tp_scatter, cudaFuncAttributeMaxDynamicSharedMemorySize, SM_TP);
    cudaFuncSetAttribute(k_lig_tp_z,   cudaFuncAttributeMaxDynamicSharedMemorySize, SM_LIG);

    dim3 gW(9, (E + 127) / 128);
    dim3 gWl(9, (EI + 127) / 128);
    dim3 gM(8, (EI + 127) / 128);

    k_transpose<<<(320 * 512 + 255) / 256, 256>>>(rw1);
    k_embed<<<(N + 7) / 8, 256>>>(x, emb_w0, emb_w1, N);

    // ---- message pass 0
    k_hid_edge<<<(E * 64 + 255) / 256, 256>>>(eattr, m0w0, pH, E);
    k_gemm<<<gW, 256>>>(pH, m0w1, pW, E, 576, 64);
    k_tp_scatter<<<(E + 31) / 32, 256, SM_TP>>>(pos, eidx, eidx + E, pW, E, 0);
    k_upd<<<(N + 7) / 8, 256>>>(u0w0, u0w1, imp0, N, degInv, 0);

    // ---- message pass 1
    k_hid_edge<<<(E * 64 + 255) / 256, 256>>>(eattr, m1w0, pH, E);
    k_gemm<<<gW, 256>>>(pH, m1w1, pW, E, 576, 64);
    k_tp_scatter<<<(E + 31) / 32, 256, SM_TP>>>(pos, eidx, eidx + E, pW, E, 1);
    k_upd<<<(N + 7) / 8, 256>>>(u1w0, u1w1, imp1, N, degInv, 1);

    // ---- final interaction
    k_prep<<<(EI * 64 + 255) / 256, 256>>>(pos, iidx, iidx + EI, lw0, rw0, EI);
    k_gemm<<<gWl, 256>>>(pHl, lw1, pW, EI, 576, 64);
    k_lig_tp_z<<<(EI + 15) / 16, 256, SM_LIG>>>(iidx, iidx + EI, pW, EI);
    k_gemm<<<gM, 256>>>(pZ, pTW, pM, EI, 512, 320);
    k_out<<<(EI * 8 + 255) / 256, 256>>>(outp, EI);
}

// round 5
// speedup vs baseline: 2.9816x; 1.0214x over previous
#include <cuda_runtime.h>
#include <stdint.h>
#include <math.h>

// ---------------------------------------------------------------------------
// InteractionPredictor e3nn-GNN forward, fp32, GEMM-restructured v2.
// ---------------------------------------------------------------------------
#define NMAX  16384
#define EMAX  122880
#define EIMAX 40960
#define EIP   40960                       // padded EI stride for Zt

__device__ float g_nodeA[NMAX * 40];
__device__ float g_nodeB[NMAX * 40];
__device__ float g_msgs [NMAX * 40];
__device__ __align__(16) float g_tw[320 * 512];           // transposed rec_w1
__device__ __align__(16) float g_Wg[(size_t)EMAX * 576];  // per-edge TP weights
__device__ __align__(16) float g_Hl[EIMAX * 64];
__device__ __align__(16) float g_Hr[EIMAX * 64];
__device__ __align__(16) float g_Zt[(size_t)320 * EIP];   // transposed Z
__device__ __align__(16) float g_M [(size_t)EIMAX * 512];
__device__ float g_rh[EIMAX * 3];

#define ACT_NORM 1.6789717f
#define PW0_8    0.025515518153991443f   // sqrt(1/24)/8  (== pw1/sqrt3/8)
#define PW1_8    0.044194173824159216f   // sqrt(1/8)/8
#define PWREC_8  0.006987712429686843f   // sqrt(1/320)/8
#define INV_SQ3  0.57735026918962576f
#define DEMB_C   37.716086f              // 1.14136 * e^2 * sqrt(20)

__device__ __forceinline__ float silu_act(float s) {
    return s / (1.f + expf(-s)) * ACT_NORM;
}

__device__ __forceinline__ void cpa16(unsigned int dst, const void* src) {
    asm volatile("cp.async.ca.shared.global [%0], [%1], 16;" :: "r"(dst), "l"(src));
}
__device__ __forceinline__ void cpa_commit() {
    asm volatile("cp.async.commit_group;");
}
__device__ __forceinline__ void cpa_wait0() {
    asm volatile("cp.async.wait_group 0;");
}

// ---------------------------------------------------------------------------
// Transpose rec_w1 [64,2560] -> TW[320,512], TW[p][k*8+w] = rw1[k][p*8+w]
// ---------------------------------------------------------------------------
__global__ void k_transpose(const float* __restrict__ rw1) {
    int idx = blockIdx.x * 256 + threadIdx.x;
    if (idx >= 320 * 512) return;
    int p = idx >> 9, r = idx & 511;
    int k = r >> 3, w = r & 7;
    g_tw[idx] = rw1[k * 2560 + p * 8 + w];
}

// ---------------------------------------------------------------------------
// Node embedding MLP + zero geo + zero msgs. One warp per node.
// ---------------------------------------------------------------------------
__global__ void k_embed(const float* __restrict__ x,
                        const float* __restrict__ w0,   // [10,64]
                        const float* __restrict__ w1,   // [64,16]
                        int N) {
    __shared__ float sh[8][64];
    int warp = threadIdx.x >> 5, lane = threadIdx.x & 31;
    int n = blockIdx.x * 8 + warp;
    if (n >= N) return;
    float xa[10];
    #pragma unroll
    for (int a = 0; a < 10; a++) xa[a] = x[n * 10 + a];
    #pragma unroll
    for (int r = 0; r < 2; r++) {
        int k = lane + r * 32;
        float s = 0.f;
        #pragma unroll
        for (int a = 0; a < 10; a++) s += xa[a] * w0[a * 64 + k];
        sh[warp][k] = silu_act(s * 0.31622776601683794f);   // 1/sqrt(10)
    }
    __syncwarp();
    if (lane < 16) {
        float s = 0.f;
        #pragma unroll
        for (int k = 0; k < 64; k++) s += sh[warp][k] * w1[k * 16 + lane];
        g_nodeA[n * 40 + lane] = s * 0.125f;                // 1/sqrt(64)
    }
    if (lane < 24) g_nodeA[n * 40 + 16 + lane] = 0.f;
    g_msgs[n * 40 + lane] = 0.f;
    if (lane < 8) g_msgs[n * 40 + 32 + lane] = 0.f;
}

// ---------------------------------------------------------------------------
// Fused msg weight GEMM: W[E,576] = silu(eattr @ mw0 /sqrt5) @ mw1.
// BM=128, BN=64, K=64 fully smem-resident, sync-free mainloop.
// ---------------------------------------------------------------------------
__global__ void __launch_bounds__(256) k_wgemm_msg(
        const float* __restrict__ eattr,
        const float* __restrict__ mw0,   // [5,64]
        const float* __restrict__ mw1,   // [64,576]
        float* __restrict__ C, int E) {
    extern __shared__ float sm[];
    float* As  = sm;               // [64][128]
    float* Bs  = As + 8192;        // [64][64]
    float* Ea  = Bs + 4096;        // [128*5]
    float* W0s = Ea + 640;         // [5*64]
    int t = threadIdx.x;
    int rowBase = blockIdx.y * 128;
    int nBase   = blockIdx.x * 64;

    // stage eattr tile + mw0
    for (int idx = t; idx < 640; idx += 256) {
        int r = idx / 5;
        Ea[idx] = (rowBase + r < E) ? eattr[(size_t)rowBase * 5 + idx] : 0.f;
    }
    if (t < 320 - 256) W0s[256 + t] = mw0[256 + t];
    W0s[t] = mw0[t];
    // stage B panel: Bs[k][n]
    #pragma unroll
    for (int i = 0; i < 16; i++) {
        int idx = t + i * 256;
        int k = idx >> 6, n = idx & 63;
        Bs[idx] = mw1[k * 576 + nBase + n];
    }
    __syncthreads();

    // H tile: thread (r = t>>1) computes k = (t&1)*32 .. +31
    {
        int r = t >> 1, kb = (t & 1) * 32;
        float ea[5];
        #pragma unroll
        for (int a = 0; a < 5; a++) ea[a] = Ea[r * 5 + a];
        #pragma unroll
        for (int kk = 0; kk < 32; kk++) {
            int k = kb + kk;
            float s = 0.f;
            #pragma unroll
            for (int a = 0; a < 5; a++) s += ea[a] * W0s[a * 64 + k];
            As[k * 128 + r] = silu_act(s * 0.4472135954999579f);   // 1/sqrt(5)
        }
    }
    __syncthreads();

    int tx = t & 15, ty = t >> 4;
    float acc[8][4] = {};
    #pragma unroll 16
    for (int k = 0; k < 64; k++) {
        float4 b4 = *(float4*)&Bs[k * 64 + tx * 4];
        float4 a0 = *(float4*)&As[k * 128 + ty * 8];
        float4 a1 = *(float4*)&As[k * 128 + ty * 8 + 4];
        float av[8] = {a0.x, a0.y, a0.z, a0.w, a1.x, a1.y, a1.z, a1.w};
        #pragma unroll
        for (int i = 0; i < 8; i++) {
            acc[i][0] += av[i] * b4.x;
            acc[i][1] += av[i] * b4.y;
            acc[i][2] += av[i] * b4.z;
            acc[i][3] += av[i] * b4.w;
        }
    }
    #pragma unroll
    for (int i = 0; i < 8; i++) {
        int r = rowBase + ty * 8 + i;
        if (r < E)
            *(float4*)(C + (size_t)r * 576 + nBase + tx * 4) =
                make_float4(acc[i][0], acc[i][1], acc[i][2], acc[i][3]);
    }
}

// ---------------------------------------------------------------------------
// K=64 GEMM, A from global row-major: C[M,576] = A[M,64] @ B[64,576].
// Whole panels in smem, sync-free mainloop.
// ---------------------------------------------------------------------------
__global__ void __launch_bounds__(256) k_gemm64(
        const float* __restrict__ A, const float* __restrict__ B,
        float* __restrict__ C, int M) {
    extern __shared__ float sm[];
    float* As = sm;                // [64][132] padded
    float* Bs = As + 64 * 132;     // [64][64]
    int t = threadIdx.x;
    int rowBase = blockIdx.y * 128;
    int nBase   = blockIdx.x * 64;
    int ar = t >> 3, ac4 = (t & 7) * 4;
    #pragma unroll
    for (int i = 0; i < 4; i++) {
        int r = rowBase + ar + 32 * i;
        #pragma unroll
        for (int h = 0; h < 2; h++) {
            int kc = ac4 + h * 32;
            float4 v = make_float4(0.f, 0.f, 0.f, 0.f);
            if (r < M) v = *(const float4*)(A + (size_t)r * 64 + kc);
            As[(kc + 0) * 132 + ar + 32 * i] = v.x;
            As[(kc + 1) * 132 + ar + 32 * i] = v.y;
            As[(kc + 2) * 132 + ar + 32 * i] = v.z;
            As[(kc + 3) * 132 + ar + 32 * i] = v.w;
        }
    }
    #pragma unroll
    for (int i = 0; i < 16; i++) {
        int idx = t + i * 256;
        int k = idx >> 6, n = idx & 63;
        Bs[idx] = B[k * 576 + nBase + n];
    }
    __syncthreads();
    int tx = t & 15, ty = t >> 4;
    float acc[8][4] = {};
    #pragma unroll 16
    for (int k = 0; k < 64; k++) {
        float4 b4 = *(float4*)&Bs[k * 64 + tx * 4];
        float4 a0 = *(float4*)&As[k * 132 + ty * 8];
        float4 a1 = *(float4*)&As[k * 132 + ty * 8 + 4];
        float av[8] = {a0.x, a0.y, a0.z, a0.w, a1.x, a1.y, a1.z, a1.w};
        #pragma unroll
        for (int i = 0; i < 8; i++) {
            acc[i][0] += av[i] * b4.x;
            acc[i][1] += av[i] * b4.y;
            acc[i][2] += av[i] * b4.z;
            acc[i][3] += av[i] * b4.w;
        }
    }
    #pragma unroll
    for (int i = 0; i < 8; i++) {
        int r = rowBase + ty * 8 + i;
        if (r < M)
            *(float4*)(C + (size_t)r * 576 + nBase + tx * 4) =
                make_float4(acc[i][0], acc[i][1], acc[i][2], acc[i][3]);
    }
}

// ---------------------------------------------------------------------------
// Rec GEMM: M[EI,512] = Z @ TW. A = Zt (K-major [320][EIP]), B = TW [320,512].
// BM=128, BN=64, BK=32, cp.async double-buffered.
// ---------------------------------------------------------------------------
__global__ void __launch_bounds__(256) k_gemm_rec(
        const float* __restrict__ Zt, const float* __restrict__ TW,
        float* __restrict__ C, int M) {
    extern __shared__ float sm[];
    float* As = sm;            // [2][32][128]
    float* Bs = As + 8192;     // [2][32][64]
    unsigned int sAs = (unsigned int)__cvta_generic_to_shared(As);
    unsigned int sBs = (unsigned int)__cvta_generic_to_shared(Bs);
    int t = threadIdx.x;
    int rowBase = blockIdx.y * 128;
    int nBase   = blockIdx.x * 64;
    int tx = t & 15, ty = t >> 4;

    // prefetch tile 0
    {
        #pragma unroll
        for (int i = 0; i < 4; i++) {
            int c = t + i * 256;                 // 1024 chunks
            int kr = c >> 5, c4 = (c & 31) * 4;
            cpa16(sAs + (kr * 128 + c4) * 4, Zt + (size_t)kr * EIP + rowBase + c4);
        }
        #pragma unroll
        for (int i = 0; i < 2; i++) {
            int c = t + i * 256;                 // 512 chunks
            int kr = c >> 4, c4 = (c & 15) * 4;
            cpa16(sBs + (kr * 64 + c4) * 4, TW + kr * 512 + nBase + c4);
        }
        cpa_commit();
    }

    float acc[8][4] = {};
    for (int it = 0; it < 10; it++) {
        cpa_wait0();
        __syncthreads();
        if (it + 1 < 10) {
            int k0 = (it + 1) * 32;
            int b = (it + 1) & 1;
            #pragma unroll
            for (int i = 0; i < 4; i++) {
                int c = t + i * 256;
                int kr = c >> 5, c4 = (c & 31) * 4;
                cpa16(sAs + (b * 4096 + kr * 128 + c4) * 4,
                      Zt + (size_t)(k0 + kr) * EIP + rowBase + c4);
            }
            #pragma unroll
            for (int i = 0; i < 2; i++) {
                int c = t + i * 256;
                int kr = c >> 4, c4 = (c & 15) * 4;
                cpa16(sBs + (b * 2048 + kr * 64 + c4) * 4,
                      TW + (k0 + kr) * 512 + nBase + c4);
            }
            cpa_commit();
        }
        const float* Ab = As + (it & 1) * 4096;
        const float* Bb = Bs + (it & 1) * 2048;
        #pragma unroll
        for (int k = 0; k < 32; k++) {
            float4 b4 = *(float4*)&Bb[k * 64 + tx * 4];
            float4 a0 = *(float4*)&Ab[k * 128 + ty * 8];
            float4 a1 = *(float4*)&Ab[k * 128 + ty * 8 + 4];
            float av[8] = {a0.x, a0.y, a0.z, a0.w, a1.x, a1.y, a1.z, a1.w};
            #pragma unroll
            for (int i = 0; i < 8; i++) {
                acc[i][0] += av[i] * b4.x;
                acc[i][1] += av[i] * b4.y;
                acc[i][2] += av[i] * b4.z;
                acc[i][3] += av[i] * b4.w;
            }
        }
        __syncthreads();
    }
    #pragma unroll
    for (int i = 0; i < 8; i++) {
        int r = rowBase + ty * 8 + i;
        if (r < M)
            *(float4*)(C + (size_t)r * 512 + nBase + tx * 4) =
                make_float4(acc[i][0], acc[i][1], acc[i][2], acc[i][3]);
    }
}

// ---------------------------------------------------------------------------
// TP + scatter: 32 edges/block.
// ---------------------------------------------------------------------------
__global__ void __launch_bounds__(256) k_tp_scatter(
        const float* __restrict__ pos,
        const int* __restrict__ src, const int* __restrict__ dst,
        const float* __restrict__ Wg, int E, int use_b) {
    extern __shared__ float sm[];
    float* sh_w   = sm;                  // 32*577 = 18464
    float* sh_f   = sh_w + 18464;        // 1280
    float* sh_dot = sh_f + 1280;         // 256
    float* sh_r   = sh_dot + 256;        // 96
    int*   sh_src = (int*)(sh_r + 96);
    int*   sh_dst = sh_src + 32;
    const float* node = use_b ? g_nodeB : g_nodeA;
    int t = threadIdx.x;
    int ebase = blockIdx.x * 32;
    int nval = min(32, E - ebase);

    if (t < 32) {
        sh_src[t] = (t < nval) ? src[ebase + t] : 0;
        sh_dst[t] = (t < nval) ? dst[ebase + t] : -1;
    }
    __syncthreads();
    for (int idx = t; idx < nval * 576; idx += 256) {
        int e = idx / 576, j = idx - e * 576;
        sh_w[e * 577 + j] = Wg[(size_t)ebase * 576 + idx];
    }
    for (int idx = t; idx < 1280; idx += 256) {
        int e = idx / 40, f = idx - e * 40;
        sh_f[idx] = (sh_dst[e] >= 0) ? node[sh_src[e] * 40 + f] : 0.f;
    }
    if (t < 32) {
        float rx = 0.f, ry = 0.f, rz = 0.f;
        if (sh_dst[t] >= 0) {
            const float* ps = pos + sh_src[t] * 3;
            const float* pd = pos + sh_dst[t] * 3;
            rx = pd[0] - ps[0]; ry = pd[1] - ps[1]; rz = pd[2] - ps[2];
            float inv = rsqrtf(rx * rx + ry * ry + rz * rz);
            rx *= inv; ry *= inv; rz *= inv;
        }
        sh_r[t * 3] = rx; sh_r[t * 3 + 1] = ry; sh_r[t * 3 + 2] = rz;
    }
    __syncthreads();
    {
        int e = t >> 3, u = t & 7;
        sh_dot[t] = sh_f[e * 40 + 16 + u * 3] * sh_r[e * 3]
                  + sh_f[e * 40 + 17 + u * 3] * sh_r[e * 3 + 1]
                  + sh_f[e * 40 + 18 + u * 3] * sh_r[e * 3 + 2];
    }
    __syncthreads();
    for (int idx = t; idx < 1280; idx += 256) {
        int e = idx / 40, o = idx - e * 40;
        int d = sh_dst[e];
        if (d < 0) continue;
        const float* w = sh_w + e * 577;
        const float* f = sh_f + e * 40;
        float val;
        if (o < 16) {
            float s1 = 0.f, s2 = 0.f;
            #pragma unroll
            for (int u = 0; u < 16; u++) s1 += f[u] * w[u * 16 + o];
            #pragma unroll
            for (int u = 0; u < 8; u++)  s2 += sh_dot[e * 8 + u] * w[256 + u * 16 + o];
            val = PW0_8 * (s1 + s2);
        } else {
            int v = o - 16; int wv = v / 3; int i = v - wv * 3;
            float s1 = 0.f, s2 = 0.f;
            #pragma unroll
            for (int u = 0; u < 16; u++) s1 += f[u] * w[384 + u * 8 + wv];
            #pragma unroll
            for (int u = 0; u < 8; u++)  s2 += f[16 + u * 3 + i] * w[512 + u * 8 + wv];
            val = PW1_8 * s1 * sh_r[e * 3 + i] + PW0_8 * s2;
        }
        atomicAdd(&g_msgs[d * 40 + o], val);
    }
}

// ---------------------------------------------------------------------------
// Update step. Re-zeroes g_msgs.
// ---------------------------------------------------------------------------
__global__ void k_upd(const float* __restrict__ uw0,   // [32,64]
                      const float* __restrict__ uw1,   // [64,16]
                      const float* __restrict__ imp,
                      int N, float degInv, int step) {
    __shared__ float cat[8][32];
    __shared__ float hh[8][64];
    int warp = threadIdx.x >> 5, lane = threadIdx.x & 31;
    int n = blockIdx.x * 8 + warp;
    if (n >= N) return;
    const float* in = step ? g_nodeB : g_nodeA;
    float* out = step ? g_nodeA : g_nodeB;
    float sc = imp[0] * degInv;
    float gscale = step ? 0.5f : 1.0f;
    if (lane < 16) {
        cat[warp][lane]      = g_msgs[n * 40 + lane] * sc;
        cat[warp][16 + lane] = in[n * 40 + lane];
    }
    __syncwarp();
    #pragma unroll
    for (int r = 0; r < 2; r++) {
        int k = lane + r * 32;
        float s = 0.f;
        #pragma unroll
        for (int a = 0; a < 32; a++) s += cat[warp][a] * uw0[a * 64 + k];
        hh[warp][k] = silu_act(s * 0.17677669529663687f);   // 1/sqrt(32)
    }
    __syncwarp();
    if (lane < 16) {
        float s = 0.f;
        #pragma unroll
        for (int k = 0; k < 64; k++) s += hh[warp][k] * uw1[k * 16 + lane];
        out[n * 40 + lane] = s * 0.125f;
    }
    if (lane < 24)
        out[n * 40 + 16 + lane] =
            (g_msgs[n * 40 + 16 + lane] * sc + in[n * 40 + 16 + lane]) * gscale;
    g_msgs[n * 40 + lane] = 0.f;
    if (lane < 8) g_msgs[n * 40 + 32 + lane] = 0.f;
}

// ---------------------------------------------------------------------------
// Inter-edge prep: rhat + dist-embed -> Hl, Hr hidden activations.
// ---------------------------------------------------------------------------
__global__ void k_prep(const float* __restrict__ pos,
                       const int* __restrict__ irec, const int* __restrict__ ilig,
                       const float* __restrict__ lw0,   // [20,64]
                       const float* __restrict__ rw0,   // [20,64]
                       int EI) {
    int idx = blockIdx.x * 256 + threadIdx.x;
    int e = idx >> 6, k = idx & 63;
    if (e >= EI) return;
    int ir = irec[e], il = ilig[e];
    float rx = pos[il * 3]     - pos[ir * 3];
    float ry = pos[il * 3 + 1] - pos[ir * 3 + 1];
    float rz = pos[il * 3 + 2] - pos[ir * 3 + 2];
    float d = sqrtf(rx * rx + ry * ry + rz * rz);
    float inv = 1.f / d;
    if (k == 0) {
        g_rh[e * 3]     = rx * inv;
        g_rh[e * 3 + 1] = ry * inv;
        g_rh[e * 3 + 2] = rz * inv;
    }
    float s1 = 0.f, s2 = 0.f;
    #pragma unroll
    for (int a = 0; a < 20; a++) {
        float diff = d * (21.f / 5.f) - (float)(a + 1);
        float t1 = diff + 1.f, t2 = 1.f - diff;
        float v = 0.f;
        if (t1 > 0.f && t2 > 0.f) v = DEMB_C * expf(-1.f / t1 - 1.f / t2);
        s1 += v * lw0[a * 64 + k];
        s2 += v * rw0[a * 64 + k];
    }
    g_Hl[idx] = silu_act(s1 * 0.22360679774997896f);   // 1/sqrt(20)
    g_Hr[idx] = silu_act(s2 * 0.22360679774997896f);
}

// ---------------------------------------------------------------------------
// lig TP + Z outer-product (writes transposed Zt): 16 inter-edges per block.
// ---------------------------------------------------------------------------
__global__ void __launch_bounds__(256) k_lig_tp_z(
        const int* __restrict__ irec, const int* __restrict__ ilig,
        const float* __restrict__ Wl, int EI) {
    extern __shared__ float sm[];
    float* sh_w   = sm;                 // 16*577 = 9232
    float* sh_fl  = sh_w + 9232;        // 640
    float* sh_fr  = sh_fl + 640;        // 640
    float* sh_dot = sh_fr + 640;        // 128
    float* sh_r   = sh_dot + 128;       // 48
    float* sh_le  = sh_r + 48;          // 640
    int* sh_il = (int*)(sh_le + 640);
    int* sh_ir = sh_il + 16;
    int t = threadIdx.x;
    int ebase = blockIdx.x * 16;
    int nval = min(16, EI - ebase);

    if (t < 16) {
        sh_ir[t] = (t < nval) ? irec[ebase + t] : 0;
        sh_il[t] = (t < nval) ? ilig[ebase + t] : 0;
    }
    __syncthreads();
    for (int idx = t; idx < nval * 576; idx += 256) {
        int e = idx / 576, j = idx - e * 576;
        sh_w[e * 577 + j] = Wl[(size_t)ebase * 576 + idx];
    }
    for (int idx = t; idx < 640; idx += 256) {
        int e = idx / 40, f = idx - e * 40;
        sh_fl[idx] = g_nodeA[sh_il[e] * 40 + f];
        sh_fr[idx] = g_nodeA[sh_ir[e] * 40 + f];
    }
    if (t < 48) {
        int e = t / 3;
        int ge = (e < nval) ? (ebase + e) : 0;
        sh_r[t] = g_rh[ge * 3 + (t - e * 3)];
    }
    __syncthreads();
    if (t < 128) {
        int e = t >> 3, u = t & 7;
        sh_dot[t] = sh_fl[e * 40 + 16 + u * 3] * sh_r[e * 3]
                  + sh_fl[e * 40 + 17 + u * 3] * sh_r[e * 3 + 1]
                  + sh_fl[e * 40 + 18 + u * 3] * sh_r[e * 3 + 2];
    }
    __syncthreads();
    for (int idx = t; idx < 640; idx += 256) {
        int e = idx / 40, o = idx - e * 40;
        const float* w = sh_w + e * 577;
        const float* f = sh_fl + e * 40;
        float val;
        if (o < 16) {
            float s1 = 0.f, s2 = 0.f;
            #pragma unroll
            for (int u = 0; u < 16; u++) s1 += f[u] * w[u * 16 + o];
            #pragma unroll
            for (int u = 0; u < 8; u++)  s2 += sh_dot[e * 8 + u] * w[256 + u * 16 + o];
            val = PW0_8 * (s1 + s2);
        } else {
            int v = o - 16; int wv = v / 3; int i = v - wv * 3;
            float s1 = 0.f, s2 = 0.f;
            #pragma unroll
            for (int u = 0; u < 16; u++) s1 += f[u] * w[384 + u * 8 + wv];
            #pragma unroll
            for (int u = 0; u < 8; u++)  s2 += f[16 + u * 3 + i] * w[512 + u * 8 + wv];
            val = PW1_8 * s1 * sh_r[e * 3 + i] + PW0_8 * s2;
        }
        sh_le[idx] = val;
    }
    __syncthreads();
    for (int idx = t; idx < 16 * 320; idx += 256) {
        int p = idx >> 4, e = idx & 15;
        if (e >= nval) continue;
        float z;
        if (p < 256) {
            z = sh_le[e * 40 + (p >> 4)] * sh_fr[e * 40 + (p & 15)];
        } else {
            int q = p - 256; int u = q >> 3, v = q & 7;
            z = (sh_le[e * 40 + 16 + u * 3] * sh_fr[e * 40 + 16 + v * 3]
               + sh_le[e * 40 + 17 + u * 3] * sh_fr[e * 40 + 17 + v * 3]
               + sh_le[e * 40 + 18 + u * 3] * sh_fr[e * 40 + 18 + v * 3]) * INV_SQ3;
        }
        g_Zt[(size_t)p * EIP + ebase + e] = z;
    }
}

// ---------------------------------------------------------------------------
// Output: out[e,w] = PWREC_8 * sum_k Hr[e,k] * M[e,k*8+w]
// ---------------------------------------------------------------------------
__global__ void k_out(float* __restrict__ outp, int EI) {
    int idx = blockIdx.x * 256 + threadIdx.x;
    int e = idx >> 3, w = idx & 7;
    if (e >= EI) return;
    float s = 0.f;
    #pragma unroll
    for (int k = 0; k < 64; k++)
        s += g_Hr[e * 64 + k] * g_M[(size_t)e * 512 + k * 8 + w];
    outp[idx] = PWREC_8 * s;
}

// ---------------------------------------------------------------------------
extern "C" void kernel_launch(void* const* d_in, const int* in_sizes, int n_in,
                              void* d_out, int out_size) {
    const float* x     = (const float*)d_in[0];
    const float* pos   = (const float*)d_in[1];
    const int*   eidx  = (const int*)  d_in[2];
    const float* eattr = (const float*)d_in[3];
    const int*   iidx  = (const int*)  d_in[4];
    const float* emb_w0= (const float*)d_in[5];
    const float* emb_w1= (const float*)d_in[6];
    const float* imp0  = (const float*)d_in[7];
    const float* m0w0  = (const float*)d_in[8];
    const float* m0w1  = (const float*)d_in[9];
    const float* u0w0  = (const float*)d_in[10];
    const float* u0w1  = (const float*)d_in[11];
    const float* imp1  = (const float*)d_in[12];
    const float* m1w0  = (const float*)d_in[13];
    const float* m1w1  = (const float*)d_in[14];
    const float* u1w0  = (const float*)d_in[15];
    const float* u1w1  = (const float*)d_in[16];
    const float* lw0   = (const float*)d_in[17];
    const float* lw1   = (const float*)d_in[18];
    const float* rw0   = (const float*)d_in[19];
    const float* rw1   = (const float*)d_in[20];
    float* outp = (float*)d_out;

    int N  = in_sizes[0] / 10;
    int E  = in_sizes[2] / 2;
    int EI = in_sizes[4] / 2;
    float degInv = (float)(1.0 / sqrt((double)E / (double)N));

    float *pW, *pZt, *pM, *pHl, *pTW;
    cudaGetSymbolAddress((void**)&pW,  g_Wg);
    cudaGetSymbolAddress((void**)&pZt, g_Zt);
    cudaGetSymbolAddress((void**)&pM,  g_M);
    cudaGetSymbolAddress((void**)&pHl, g_Hl);
    cudaGetSymbolAddress((void**)&pTW, g_tw);

    const int SM_MSGG = (8192 + 4096 + 640 + 320) * 4;                   // 52992
    const int SM_G64  = (64 * 132 + 4096) * 4;                           // 50176
    const int SM_REC  = (8192 + 4096) * 4;                               // 49152
    const int SM_TP   = (18464 + 1280 + 256 + 96) * 4 + 64 * 4;          // 80640
    const int SM_LIG  = (9232 + 640 + 640 + 128 + 48 + 640) * 4 + 32 * 4;
    cudaFuncSetAttribute(k_wgemm_msg, cudaFuncAttributeMaxDynamicSharedMemorySize, SM_MSGG);
    cudaFuncSetAttribute(k_gemm64,    cudaFuncAttributeMaxDynamicSharedMemorySize, SM_G64);
    cudaFuncSetAttribute(k_gemm_rec,  cudaFuncAttributeMaxDynamicSharedMemorySize, SM_REC);
    cudaFuncSetAttribute(k_tp_scatter, cudaFuncAttributeMaxDynamicSharedMemorySize, SM_TP);
    cudaFuncSetAttribute(k_lig_tp_z,   cudaFuncAttributeMaxDynamicSharedMemorySize, SM_LIG);

    dim3 gW(9, (E + 127) / 128);
    dim3 gWl(9, (EI + 127) / 128);
    dim3 gM(8, (EI + 127) / 128);

    k_transpose<<<(320 * 512 + 255) / 256, 256>>>(rw1);
    k_embed<<<(N + 7) / 8, 256>>>(x, emb_w0, emb_w1, N);

    // ---- message pass 0
    k_wgemm_msg<<<gW, 256, SM_MSGG>>>(eattr, m0w0, m0w1, pW, E);
    k_tp_scatter<<<(E + 31) / 32, 256, SM_TP>>>(pos, eidx, eidx + E, pW, E, 0);
    k_upd<<<(N + 7) / 8, 256>>>(u0w0, u0w1, imp0, N, degInv, 0);

    // ---- message pass 1
    k_wgemm_msg<<<gW, 256, SM_MSGG>>>(eattr, m1w0, m1w1, pW, E);
    k_tp_scatter<<<(E + 31) / 32, 256, SM_TP>>>(pos, eidx, eidx + E, pW, E, 1);
    k_upd<<<(N + 7) / 8, 256>>>(u1w0, u1w1, imp1, N, degInv, 1);

    // ---- final interaction
    k_prep<<<(EI * 64 + 255) / 256, 256>>>(pos, iidx, iidx + EI, lw0, rw0, EI);
    k_gemm64<<<gWl, 256, SM_G64>>>(pHl, lw1, pW, EI);
    k_lig_tp_z<<<(EI + 15) / 16, 256, SM_LIG>>>(iidx, iidx + EI, pW, EI);
    k_gemm_rec<<<gM, 256, SM_REC>>>(pZt, pTW, pM, EI);
    k_out<<<(EI * 8 + 255) / 256, 256>>>(outp, EI);
}